// round 17
// baseline (speedup 1.0000x reference)
#include <cuda_runtime.h>
#include <cuda_bf16.h>
#include <cstdint>
#include <cstddef>

#define T_STEPS 512
#define B_SZ    256
#define NO_SZ   128

// ---------------------------------------------------------------------------
// Static scratch.
//   g_G   [tile][b][r]   fp32 preacts (contrib/gsum fold sources in place)
//   g_Hep [tile][b][k]   fp32 hidden epochs
//   g_R   [tile][b][o]   prefix-summed output projections
//   g_C   [ctile][b][r]  off-diagonal recurrent projections
// ---------------------------------------------------------------------------
__device__ float g_G  [1020u * 64  * 256];
__device__ float g_Hep[1020u * 64  * 256];
__device__ float g_R  [1020u * 128 * 256];
__device__ float g_C  [988u  * 64  * 256];

__device__ __constant__ int c_S[8] = {0, 0, 256, 512, 704, 832, 912, 960};

__device__ __forceinline__ int hb(int j) { return 1024 - (1024 >> j); }

__device__ __forceinline__ float ftanh(float x) {
    float t = __expf(2.0f * x);
    return 1.0f - __fdividef(2.0f, t + 1.0f);
}

// ---------------------------------------------------------------------------
// bf16 MMA machinery
// ---------------------------------------------------------------------------
__device__ __forceinline__ void mma_bf16(float* d, const uint32_t* a, const uint32_t* b)
{
    asm volatile(
        "mma.sync.aligned.m16n8k16.row.col.f32.bf16.bf16.f32 "
        "{%0,%1,%2,%3},{%4,%5,%6,%7},{%8,%9},{%0,%1,%2,%3};\n"
        : "+f"(d[0]), "+f"(d[1]), "+f"(d[2]), "+f"(d[3])
        : "r"(a[0]), "r"(a[1]), "r"(a[2]), "r"(a[3]), "r"(b[0]), "r"(b[1]));
}

__device__ __forceinline__ uint32_t pack2(float x0, float x1, bool lo)
{
    __nv_bfloat16 h0 = __float2bfloat16(x0);
    __nv_bfloat16 h1 = __float2bfloat16(x1);
    if (lo) {
        h0 = __float2bfloat16(x0 - __bfloat162float(h0));
        h1 = __float2bfloat16(x1 - __bfloat162float(h1));
    }
    __nv_bfloat162 p = __halves2bfloat162(h0, h1);
    return *reinterpret_cast<uint32_t*>(&p);
}

#define AH_OFF 0
#define AL_OFF 2304
#define BH_OFF 4608
#define BL_OFF 6912

__device__ __forceinline__ void stage_AB(uint32_t* su,
                                         const float* __restrict__ Ag, int lda, int koff,
                                         const float* __restrict__ Bg, int ldb,
                                         int tid)
{
    for (int idx = tid; idx < 64 * 32; idx += 256) {
        int r = idx >> 5, p = idx & 31;
        float x0 = Ag[(size_t)r * lda + koff + 2 * p];
        float x1 = Ag[(size_t)r * lda + koff + 2 * p + 1];
        su[AH_OFF + r * 36 + p] = pack2(x0, x1, false);
        su[AL_OFF + r * 36 + p] = pack2(x0, x1, true);
    }
    for (int idx = tid; idx < 64 * 16; idx += 256) {
        int c = idx >> 4, q = idx & 15;
        float4 v = *(const float4*)&Bg[(size_t)c * ldb + koff + 4 * q];
        su[BH_OFF + c * 36 + 2 * q]     = pack2(v.x, v.y, false);
        su[BL_OFF + c * 36 + 2 * q]     = pack2(v.x, v.y, true);
        su[BH_OFF + c * 36 + 2 * q + 1] = pack2(v.z, v.w, false);
        su[BL_OFF + c * 36 + 2 * q + 1] = pack2(v.z, v.w, true);
    }
}

__device__ __forceinline__ void mma_block(const uint32_t* su, int warp, int lane,
                                          float (&acc)[4][4])
{
    const int mrow = (warp & 3) * 16;
    const int nb   = (warp >> 2) * 32;
    const int gr   = lane >> 2, tg = lane & 3;
#pragma unroll
    for (int c = 0; c < 4; c++) {
        const int pb = c * 8;
        uint32_t ah[4], al[4];
        ah[0] = su[AH_OFF + (mrow + gr)     * 36 + pb + tg];
        ah[1] = su[AH_OFF + (mrow + gr + 8) * 36 + pb + tg];
        ah[2] = su[AH_OFF + (mrow + gr)     * 36 + pb + 4 + tg];
        ah[3] = su[AH_OFF + (mrow + gr + 8) * 36 + pb + 4 + tg];
        al[0] = su[AL_OFF + (mrow + gr)     * 36 + pb + tg];
        al[1] = su[AL_OFF + (mrow + gr + 8) * 36 + pb + tg];
        al[2] = su[AL_OFF + (mrow + gr)     * 36 + pb + 4 + tg];
        al[3] = su[AL_OFF + (mrow + gr + 8) * 36 + pb + 4 + tg];
#pragma unroll
        for (int nt = 0; nt < 4; nt++) {
            const int colb = nb + nt * 8 + gr;
            uint32_t bh[2], bl[2];
            bh[0] = su[BH_OFF + colb * 36 + pb + tg];
            bh[1] = su[BH_OFF + colb * 36 + pb + 4 + tg];
            bl[0] = su[BL_OFF + colb * 36 + pb + tg];
            bl[1] = su[BL_OFF + colb * 36 + pb + 4 + tg];
            mma_bf16(acc[nt], ah, bh);
            mma_bf16(acc[nt], ah, bl);
            mma_bf16(acc[nt], al, bh);
        }
    }
}

__device__ __forceinline__ void acc_to_S(float* Sf, int warp, int lane, float (&acc)[4][4])
{
    const int mrow = (warp & 3) * 16;
    const int nb   = (warp >> 2) * 32;
    const int gr   = lane >> 2, tg = lane & 3;
#pragma unroll
    for (int nt = 0; nt < 4; nt++) {
        const int c0 = nb + nt * 8 + 2 * tg;
        Sf[(size_t)c0       * 68 + mrow + gr]     = acc[nt][0];
        Sf[(size_t)(c0 + 1) * 68 + mrow + gr]     = acc[nt][1];
        Sf[(size_t)c0       * 68 + mrow + gr + 8] = acc[nt][2];
        Sf[(size_t)(c0 + 1) * 68 + mrow + gr + 8] = acc[nt][3];
    }
}

// ---------------------------------------------------------------------------
// g0: G[c][m] = Wi_c @ x_{m<<c} + biases.  grid (ntiles, 4), 256 thr.
// ---------------------------------------------------------------------------
__global__ void __launch_bounds__(256) g0_kernel(const float* __restrict__ X,
                                                 const float* __restrict__ Wi,
                                                 const float* __restrict__ Wh,
                                                 int idx0)
{
    __shared__ __align__(16) uint32_t su[9216];
    float* Sf = (float*)(su + BH_OFF);

    const int idx = idx0 + blockIdx.x;
    const int v   = 1024 - idx;
    const int c   = __clz(v - 1) - 22;
    const int m   = idx - (1024 - (1024 >> c));
    const int t   = m << c;
    const int b0  = blockIdx.y * 64;
    const int tid = threadIdx.x;
    const int warp = tid >> 5, lane = tid & 31;

    const float* Ag = Wi + (size_t)(c * 64) * 129;
    const float* Bg = X + ((size_t)t * 256 + b0) * 128;

    float acc[4][4];
#pragma unroll
    for (int q = 0; q < 4; q++)
#pragma unroll
        for (int u = 0; u < 4; u++) acc[q][u] = 0.f;

    for (int kh = 0; kh < 2; kh++) {
        stage_AB(su, Ag, 129, kh * 64, Bg, 128, tid);
        __syncthreads();
        mma_block(su, warp, lane, acc);
        __syncthreads();
    }

    {
        const int mrow = (warp & 3) * 16, gr = lane >> 2;
        int r0 = c * 64 + mrow + gr, r1 = r0 + 8;
        float ba = Wi[(size_t)r0 * 129 + 128] + Wh[(size_t)r0 * 513 + 512];
        float bb = Wi[(size_t)r1 * 129 + 128] + Wh[(size_t)r1 * 513 + 512];
#pragma unroll
        for (int nt = 0; nt < 4; nt++) {
            acc[nt][0] += ba; acc[nt][1] += ba;
            acc[nt][2] += bb; acc[nt][3] += bb;
        }
    }

    acc_to_S(Sf, warp, lane, acc);
    __syncthreads();

    float* out = g_G + (size_t)idx * 16384 + (size_t)b0 * 64;
    for (int i = tid; i < 64 * 16; i += 256) {
        int col = i >> 4, rq = i & 15;
        *(float4*)&out[(size_t)col * 64 + rq * 4] = *(float4*)&Sf[(size_t)col * 68 + rq * 4];
    }
}

// ---------------------------------------------------------------------------
// projC: C[z][j][e] = Wh[z-rows, j-cols] @ H_j[e],  z = zbase + blockIdx.z.
// ---------------------------------------------------------------------------
__global__ void __launch_bounds__(256) projC_kernel(const float* __restrict__ Wh,
                                                    int j, int zbase)
{
    __shared__ __align__(16) uint32_t su[9216];
    float* Sf = (float*)(su + BH_OFF);

    const int e   = blockIdx.x;
    const int U   = gridDim.x;
    const int b0  = blockIdx.y * 64;
    const int z   = zbase + blockIdx.z;
    const int tid = threadIdx.x;
    const int warp = tid >> 5, lane = tid & 31;

    const float* Ag = Wh + (size_t)(z * 64) * 513 + j * 64;
    const float* Bg = g_Hep + (size_t)(hb(j) + e) * 16384 + (size_t)b0 * 64;

    float acc[4][4];
#pragma unroll
    for (int q = 0; q < 4; q++)
#pragma unroll
        for (int u = 0; u < 4; u++) acc[q][u] = 0.f;

    stage_AB(su, Ag, 513, 0, Bg, 64, tid);
    __syncthreads();
    mma_block(su, warp, lane, acc);
    __syncthreads();
    acc_to_S(Sf, warp, lane, acc);
    __syncthreads();

    float* out = g_C + (size_t)(c_S[j] + z * U + e) * 16384 + (size_t)b0 * 64;
    for (int i = tid; i < 64 * 16; i += 256) {
        int col = i >> 4, rq = i & 15;
        *(float4*)&out[(size_t)col * 64 + rq * 4] =
            *(float4*)&Sf[(size_t)col * 68 + rq * 4];
    }
}

// ---------------------------------------------------------------------------
// gsum: G'[m] = G[m] + sum_{j in [jlo, jhi)} C[C][j][(m-1)>>(j-C)]  (m >= 1)
// ---------------------------------------------------------------------------
__global__ void __launch_bounds__(256) gsum_kernel(int C, int jlo, int jhi)
{
    const int m   = blockIdx.x + 1;
    const int b0  = blockIdx.y * 64;
    const int tid = threadIdx.x;
    const int HB  = 1024 - (1024 >> C);

    float* Gt = g_G + (size_t)(HB + m) * 16384 + (size_t)b0 * 64;

    const float* Ct[6];
    int ns = 0;
    for (int j = jlo; j < jhi; j++) {
        int e = (m - 1) >> (j - C);
        Ct[ns++] = g_C + (size_t)(c_S[j] + C * (512 >> j) + e) * 16384 + (size_t)b0 * 64;
    }

    for (int i = tid; i < 1024; i += 256) {
        float4 a = *(float4*)&Gt[i * 4];
        for (int s = 0; s < ns; s++) {
            float4 v = *(const float4*)&Ct[s][i * 4];
            a.x += v.x; a.y += v.y; a.z += v.z; a.w += v.w;
        }
        *(float4*)&Gt[i * 4] = a;
    }
}

// ---------------------------------------------------------------------------
// projR: R_j[e] rows z*64.. = Wo[rows, j-cols] @ H_j[e] + R_{j+1}[e>>1]
//        (+Wo bias at j=7; tanh->Y at j=0).
// ---------------------------------------------------------------------------
__global__ void __launch_bounds__(256) projR_kernel(const float* __restrict__ Wo,
                                                    float* __restrict__ Y, int j)
{
    __shared__ __align__(16) uint32_t su[9216];
    float* Sf = (float*)(su + BH_OFF);

    const int e   = blockIdx.x;
    const int b0  = blockIdx.y * 64;
    const int z   = blockIdx.z;
    const int tid = threadIdx.x;
    const int warp = tid >> 5, lane = tid & 31;

    const float* Ag = Wo + (size_t)(z * 64) * 513 + j * 64;
    const float* Bg = g_Hep + (size_t)(hb(j) + e) * 16384 + (size_t)b0 * 64;

    float acc[4][4];
#pragma unroll
    for (int q = 0; q < 4; q++)
#pragma unroll
        for (int u = 0; u < 4; u++) acc[q][u] = 0.f;

    stage_AB(su, Ag, 513, 0, Bg, 64, tid);
    __syncthreads();
    mma_block(su, warp, lane, acc);
    __syncthreads();
    acc_to_S(Sf, warp, lane, acc);
    __syncthreads();

    const int o0 = z * 64;
    const float* Rpar = (j < 7)
        ? g_R + (size_t)(hb(j + 1) + (e >> 1)) * 32768
        : nullptr;
    for (int i = tid; i < 64 * 16; i += 256) {
        int col = i >> 4, rq = i & 15;
        float4 s = *(float4*)&Sf[(size_t)col * 68 + rq * 4];
        if (j < 7) {
            float4 p = *(const float4*)&Rpar[(size_t)(b0 + col) * 128 + o0 + rq * 4];
            s.x += p.x; s.y += p.y; s.z += p.z; s.w += p.w;
        } else {
            s.x += Wo[(size_t)(o0 + rq * 4 + 0) * 513 + 512];
            s.y += Wo[(size_t)(o0 + rq * 4 + 1) * 513 + 512];
            s.z += Wo[(size_t)(o0 + rq * 4 + 2) * 513 + 512];
            s.w += Wo[(size_t)(o0 + rq * 4 + 3) * 513 + 512];
        }
        if (j == 0) {
            float4 y = make_float4(ftanh(s.x), ftanh(s.y), ftanh(s.z), ftanh(s.w));
            *(float4*)&Y[((size_t)e * 256 + b0 + col) * 128 + o0 + rq * 4] = y;
        } else {
            *(float4*)&g_R[(size_t)(hb(j) + e) * 32768 +
                           (size_t)(b0 + col) * 128 + o0 + rq * 4] = s;
        }
    }
}

// ---------------------------------------------------------------------------
// seq phase: one level's recurrence.  NOC1 => all external input pre-folded
// into G (seqtop).  Hsave != nullptr => also store epochs to SMEM [e][lb][k].
// ---------------------------------------------------------------------------
template <int C, bool NOC1>
__device__ __forceinline__ void seq_phase(const float* __restrict__ Wh,
                                          float (*Ws)[65], float (*Hs)[2][64],
                                          float* Hsave,
                                          int tid, int lb, int r, int off)
{
    constexpr int  U    = 512 >> C;
    constexpr bool HASC = (C < 7) && !NOC1;
    constexpr int  HB   = 1024 - (1024 >> C);
    constexpr int  csl[8] = {0, 0, 256, 512, 704, 832, 912, 960};
    constexpr int  C1B  = (C < 7) ? (csl[C + 1] + C * (512 >> (C + 1))) : 0;
    constexpr int  D    = (U < 8) ? U : 8;

    __syncthreads();   // prior users of Ws/Hs done
    for (int i = tid; i < 4096; i += 128)
        Ws[i >> 6][i & 63] = Wh[(size_t)(C * 64 + (i >> 6)) * 513 + C * 64 + (i & 63)];
    __syncthreads();

    float w[64];
#pragma unroll
    for (int q = 0; q < 64; q++) w[q] = Ws[r][q];

    const float* Gb  = g_G + (size_t)HB * 16384;
    const float* Cb  = g_C + (size_t)C1B * 16384;
    float*       Hbp = g_Hep + (size_t)HB * 16384;

    float gv[D], cv[D];
#pragma unroll
    for (int i = 0; i < D; i++) {
        gv[i] = Gb[(size_t)i * 16384 + off];
        cv[i] = 0.f;
        if (HASC && i >= 1) cv[i] = Cb[(size_t)((i - 1) >> 1) * 16384 + off];
    }

    for (int m0 = 0; m0 < U; m0 += D) {
#pragma unroll
        for (int i = 0; i < D; i++) {
            const int m  = m0 + i;
            const int rb = m & 1;
            float a = gv[i];
            if (m > 0) {
                float a0 = 0.f, a1 = 0.f, a2 = 0.f, a3 = 0.f;
#pragma unroll
                for (int q = 0; q < 64; q += 4) {
                    float4 hv = *(const float4*)&Hs[rb][lb][q];
                    a0 += w[q + 0] * hv.x;
                    a1 += w[q + 1] * hv.y;
                    a2 += w[q + 2] * hv.z;
                    a3 += w[q + 3] * hv.w;
                }
                a += (a0 + a1) + (a2 + a3);
                if (HASC) a += cv[i];
            }
            float h = ftanh(a);
            Hbp[(size_t)m * 16384 + off] = h;
            Hs[rb ^ 1][lb][r] = h;
            if (Hsave) Hsave[(size_t)(m * 2 + lb) * 64 + r] = h;
            const int mf = m + D;
            if (mf < U) {
                gv[i] = Gb[(size_t)mf * 16384 + off];
                if (HASC) cv[i] = Cb[(size_t)((mf - 1) >> 1) * 16384 + off];
            }
            __syncthreads();
        }
    }
}

// Standalone seq kernel (levels 3..0 spine + fallback).
template <int C>
__global__ void __launch_bounds__(128) seq_kernel(const float* __restrict__ Wh)
{
    __shared__ float Ws[64][65];
    __shared__ float Hs[2][2][64];
    const int tid = threadIdx.x;
    const int lb  = tid >> 6;
    const int r   = tid & 63;
    const int off = (blockIdx.x * 2 + lb) * 64 + r;
    seq_phase<C, false>(Wh, Ws, Hs, nullptr, tid, lb, r, off);
}

// ---------------------------------------------------------------------------
// contrib: fold source level j's epochs (in SMEM) into consumer z's G for
// this CTA's own columns:  G[z][m] += Wh[z-rows, j-cols] @ H_j[(m-1)>>(j-z)].
// Same-thread RMW on own elements only; no cross-CTA traffic.
// ---------------------------------------------------------------------------
__device__ __forceinline__ void contrib(const float* __restrict__ Wh,
                                        float (*Ws)[65],
                                        const float* __restrict__ Hsave_j,
                                        int z, int j, int tid, int lb, int r, int off)
{
    const int Uz  = 512 >> z;
    const int sh  = j - z;
    const int Ue  = ((Uz - 2) >> sh) + 1;
    const int HBz = 1024 - (1024 >> z);

    __syncthreads();
    for (int i = tid; i < 4096; i += 128)
        Ws[i >> 6][i & 63] = Wh[(size_t)(z * 64 + (i >> 6)) * 513 + j * 64 + (i & 63)];
    __syncthreads();

    for (int e = 0; e < Ue; e++) {
        const float* hv = Hsave_j + (size_t)(e * 2 + lb) * 64;
        float a0 = 0.f, a1 = 0.f, a2 = 0.f, a3 = 0.f;
#pragma unroll
        for (int k = 0; k < 64; k += 4) {
            a0 += Ws[r][k + 0] * hv[k + 0];
            a1 += Ws[r][k + 1] * hv[k + 1];
            a2 += Ws[r][k + 2] * hv[k + 2];
            a3 += Ws[r][k + 3] * hv[k + 3];
        }
        float dot = (a0 + a1) + (a2 + a3);
        int mlo = (e << sh) + 1;
        int mhi = (e + 1) << sh;
        if (mhi > Uz - 1) mhi = Uz - 1;
        for (int m = mlo; m <= mhi; m++)
            g_G[(size_t)(HBz + m) * 16384 + off] += dot;
    }
}

// ---------------------------------------------------------------------------
// seqtop: levels 7,6,5,4 fused in ONE kernel (60 sequential steps).  All
// cross-level inputs for levels 6..4 computed in-kernel; CTAs independent.
// Static SMEM: 16.6K (Ws) + 1K (Hs) + 2K/4K/8K (H7/H6/H5) = 32KB.
// ---------------------------------------------------------------------------
__global__ void __launch_bounds__(128) seqtop_kernel(const float* __restrict__ Wh)
{
    __shared__ float Ws[64][65];
    __shared__ float Hs[2][2][64];
    __shared__ float H7[4 * 2 * 64];
    __shared__ float H6[8 * 2 * 64];
    __shared__ float H5[16 * 2 * 64];

    const int tid = threadIdx.x;
    const int lb  = tid >> 6;
    const int r   = tid & 63;
    const int off = (blockIdx.x * 2 + lb) * 64 + r;

    seq_phase<7, true>(Wh, Ws, Hs, H7, tid, lb, r, off);
    contrib(Wh, Ws, H7, 6, 7, tid, lb, r, off);
    contrib(Wh, Ws, H7, 5, 7, tid, lb, r, off);
    contrib(Wh, Ws, H7, 4, 7, tid, lb, r, off);

    seq_phase<6, true>(Wh, Ws, Hs, H6, tid, lb, r, off);
    contrib(Wh, Ws, H6, 5, 6, tid, lb, r, off);
    contrib(Wh, Ws, H6, 4, 6, tid, lb, r, off);

    seq_phase<5, true>(Wh, Ws, Hs, H5, tid, lb, r, off);
    contrib(Wh, Ws, H5, 4, 5, tid, lb, r, off);

    seq_phase<4, true>(Wh, Ws, Hs, nullptr, tid, lb, r, off);
}

// ---------------------------------------------------------------------------
// final H: out[T*B*NO + (j*64+r)*256 + b] = H_j[last epoch][b][r] (transpose)
// ---------------------------------------------------------------------------
__global__ void __launch_bounds__(256) finalH_kernel(float* __restrict__ out)
{
    __shared__ float S[64][65];
    const int j   = blockIdx.x;
    const int b0  = blockIdx.y * 64;
    const int tid = threadIdx.x;
    const int e   = (512 >> j) - 1;
    const float* Hj = g_Hep + (size_t)(hb(j) + e) * 16384;

    for (int i = tid; i < 4096; i += 256) {
        int rr = i & 63, bb = i >> 6;
        S[bb][rr] = Hj[(size_t)(b0 + bb) * 64 + rr];
    }
    __syncthreads();
    for (int i = tid; i < 4096; i += 256) {
        int bb = i & 63, rr = i >> 6;
        out[(size_t)T_STEPS * B_SZ * NO_SZ + (size_t)(j * 64 + rr) * 256 + b0 + bb] =
            S[bb][rr];
    }
}

// ---------------------------------------------------------------------------
// Launch (event-DAG only; no spin-waits, no priorities).
//   cap: g0_hi -> seqtop -> [urgent projC / gsum gates] seq3..seq0 -> finalH
//   s1 : g0_lo (levels 3..0)
//   s2 : projR 7..4 after evTop, then per-level after evH[3..0]
//   s3 : deferred projC (sources 7..4) + gsum phases
// ---------------------------------------------------------------------------
static cudaStream_t s_s1 = nullptr, s_s2 = nullptr, s_s3 = nullptr;
static cudaEvent_t  s_ev0, s_evG0, s_evTop, s_evH[4], s_evGS[4], s_evR0;
static int s_state = 0;

static bool ensure_streams()
{
    if (s_state) return s_state > 0;
    bool ok = true;
    ok &= cudaStreamCreateWithFlags(&s_s1, cudaStreamNonBlocking) == cudaSuccess;
    ok &= cudaStreamCreateWithFlags(&s_s2, cudaStreamNonBlocking) == cudaSuccess;
    ok &= cudaStreamCreateWithFlags(&s_s3, cudaStreamNonBlocking) == cudaSuccess;
    ok &= cudaEventCreateWithFlags(&s_ev0,   cudaEventDisableTiming) == cudaSuccess;
    ok &= cudaEventCreateWithFlags(&s_evG0,  cudaEventDisableTiming) == cudaSuccess;
    ok &= cudaEventCreateWithFlags(&s_evTop, cudaEventDisableTiming) == cudaSuccess;
    ok &= cudaEventCreateWithFlags(&s_evR0,  cudaEventDisableTiming) == cudaSuccess;
    for (int i = 0; i < 4; i++) {
        ok &= cudaEventCreateWithFlags(&s_evH[i],  cudaEventDisableTiming) == cudaSuccess;
        ok &= cudaEventCreateWithFlags(&s_evGS[i], cudaEventDisableTiming) == cudaSuccess;
    }
    s_state = ok ? 1 : -1;
    return ok;
}

extern "C" void kernel_launch(void* const* d_in, const int* in_sizes, int n_in,
                              void* d_out, int out_size)
{
    const float* X  = nullptr;
    const float* Wi = nullptr;
    const float* Wh = nullptr;
    const float* Wo = nullptr;
    for (int i = 0; i < n_in; i++) {
        switch (in_sizes[i]) {
            case 512 * 256 * 128: X  = (const float*)d_in[i]; break;
            case 512 * 129:       Wi = (const float*)d_in[i]; break;
            case 512 * 513:       Wh = (const float*)d_in[i]; break;
            case 128 * 513:       Wo = (const float*)d_in[i]; break;
            default: break;
        }
    }
    float* out = (float*)d_out;

    if (!ensure_streams()) {
        // -------- Fallback: single-stream chain (R12 ordering) --------------
        g0_kernel<<<dim3(1020, 4), 256>>>(X, Wi, Wh, 0);
        seq_kernel<7><<<128, 128>>>(Wh);
        projR_kernel<<<dim3(4, 4, 2), 256>>>(Wo, out, 7);
        projC_kernel<<<dim3(4, 4, 7), 256>>>(Wh, 7, 0);
        seq_kernel<6><<<128, 128>>>(Wh);
        projR_kernel<<<dim3(8, 4, 2), 256>>>(Wo, out, 6);
        projC_kernel<<<dim3(8, 4, 6), 256>>>(Wh, 6, 0);
        gsum_kernel<<<dim3(15, 4), 256>>>(5, 7, 8);
        seq_kernel<5><<<128, 128>>>(Wh);
        projR_kernel<<<dim3(16, 4, 2), 256>>>(Wo, out, 5);
        projC_kernel<<<dim3(16, 4, 5), 256>>>(Wh, 5, 0);
        gsum_kernel<<<dim3(31, 4), 256>>>(4, 6, 8);
        seq_kernel<4><<<128, 128>>>(Wh);
        projR_kernel<<<dim3(32, 4, 2), 256>>>(Wo, out, 4);
        projC_kernel<<<dim3(32, 4, 4), 256>>>(Wh, 4, 0);
        gsum_kernel<<<dim3(63, 4), 256>>>(3, 5, 8);
        seq_kernel<3><<<128, 128>>>(Wh);
        projR_kernel<<<dim3(64, 4, 2), 256>>>(Wo, out, 3);
        projC_kernel<<<dim3(64, 4, 3), 256>>>(Wh, 3, 0);
        gsum_kernel<<<dim3(127, 4), 256>>>(2, 4, 8);
        seq_kernel<2><<<128, 128>>>(Wh);
        projR_kernel<<<dim3(128, 4, 2), 256>>>(Wo, out, 2);
        projC_kernel<<<dim3(128, 4, 2), 256>>>(Wh, 2, 0);
        gsum_kernel<<<dim3(255, 4), 256>>>(1, 3, 8);
        seq_kernel<1><<<128, 128>>>(Wh);
        projR_kernel<<<dim3(256, 4, 2), 256>>>(Wo, out, 1);
        projC_kernel<<<dim3(256, 4, 1), 256>>>(Wh, 1, 0);
        gsum_kernel<<<dim3(511, 4), 256>>>(0, 2, 8);
        seq_kernel<0><<<128, 128>>>(Wh);
        projR_kernel<<<dim3(512, 4, 2), 256>>>(Wo, out, 0);
        finalH_kernel<<<dim3(8, 4), 256>>>(out);
        return;
    }

    cudaStream_t s1 = s_s1, s2 = s_s2, s3 = s_s3;

    // Fork: g0_lo (levels 3..0, tiles 0..959) on s1.
    cudaEventRecord(s_ev0, 0);
    cudaStreamWaitEvent(s1, s_ev0, 0);
    g0_kernel<<<dim3(960, 4), 256, 0, s1>>>(X, Wi, Wh, 0);
    cudaEventRecord(s_evG0, s1);

    // Spine: g0_hi (levels 7..4) then the fused top levels.
    g0_kernel<<<dim3(60, 4), 256>>>(X, Wi, Wh, 960);
    seqtop_kernel<<<128, 128>>>(Wh);
    cudaEventRecord(s_evTop, 0);

    // s2: projR for levels 7..4 (all H ready at evTop).
    cudaStreamWaitEvent(s2, s_evTop, 0);
    projR_kernel<<<dim3(4, 4, 2), 256, 0, s2>>>(Wo, out, 7);
    projR_kernel<<<dim3(8, 4, 2), 256, 0, s2>>>(Wo, out, 6);
    projR_kernel<<<dim3(16, 4, 2), 256, 0, s2>>>(Wo, out, 5);
    projR_kernel<<<dim3(32, 4, 2), 256, 0, s2>>>(Wo, out, 4);

    // s3: all deferred projC from sources 7..4, then gsum phase-A work.
    cudaStreamWaitEvent(s3, s_evTop, 0);
    projC_kernel<<<dim3(4, 4, 4), 256, 0, s3>>>(Wh, 7, 0);   // cons 0..3
    projC_kernel<<<dim3(8, 4, 4), 256, 0, s3>>>(Wh, 6, 0);   // cons 0..3
    projC_kernel<<<dim3(16, 4, 4), 256, 0, s3>>>(Wh, 5, 0);  // cons 0..3
    projC_kernel<<<dim3(32, 4, 3), 256, 0, s3>>>(Wh, 4, 0);  // cons 0..2
    cudaStreamWaitEvent(s3, s_evG0, 0);                      // gsum RMWs g0_lo G
    gsum_kernel<<<dim3(63, 4), 256, 0, s3>>>(3, 5, 8);
    cudaEventRecord(s_evGS[3], s3);
    gsum_kernel<<<dim3(127, 4), 256, 0, s3>>>(2, 4, 8);
    cudaEventRecord(s_evGS[2], s3);
    gsum_kernel<<<dim3(255, 4), 256, 0, s3>>>(1, 4, 8);      // gsum<1> phase A
    gsum_kernel<<<dim3(511, 4), 256, 0, s3>>>(0, 4, 8);      // gsum<0> phase A

    // Spine level 3: urgent C1 (source 4, consumer 3) then seq3.
    projC_kernel<<<dim3(32, 4, 1), 256>>>(Wh, 4, 3);
    cudaStreamWaitEvent(0, s_evGS[3], 0);
    seq_kernel<3><<<128, 128>>>(Wh);
    cudaEventRecord(s_evH[3], 0);
    cudaStreamWaitEvent(s2, s_evH[3], 0);
    projR_kernel<<<dim3(64, 4, 2), 256, 0, s2>>>(Wo, out, 3);
    cudaStreamWaitEvent(s3, s_evH[3], 0);
    projC_kernel<<<dim3(64, 4, 2), 256, 0, s3>>>(Wh, 3, 0);  // cons 0..1
    gsum_kernel<<<dim3(255, 4), 256, 0, s3>>>(1, 3, 4);      // gsum<1> phase B
    cudaEventRecord(s_evGS[1], s3);
    gsum_kernel<<<dim3(511, 4), 256, 0, s3>>>(0, 3, 4);      // gsum<0> phase B1

    // Spine level 2.
    projC_kernel<<<dim3(64, 4, 1), 256>>>(Wh, 3, 2);         // urgent C1 for 2
    cudaStreamWaitEvent(0, s_evGS[2], 0);
    seq_kernel<2><<<128, 128>>>(Wh);
    cudaEventRecord(s_evH[2], 0);
    cudaStreamWaitEvent(s2, s_evH[2], 0);
    projR_kernel<<<dim3(128, 4, 2), 256, 0, s2>>>(Wo, out, 2);
    cudaStreamWaitEvent(s3, s_evH[2], 0);
    projC_kernel<<<dim3(128, 4, 1), 256, 0, s3>>>(Wh, 2, 0); // cons 0
    gsum_kernel<<<dim3(511, 4), 256, 0, s3>>>(0, 2, 3);      // gsum<0> phase B2
    cudaEventRecord(s_evGS[0], s3);

    // Spine level 1.
    projC_kernel<<<dim3(128, 4, 1), 256>>>(Wh, 2, 1);        // urgent C1 for 1
    cudaStreamWaitEvent(0, s_evGS[1], 0);
    seq_kernel<1><<<128, 128>>>(Wh);
    cudaEventRecord(s_evH[1], 0);
    cudaStreamWaitEvent(s2, s_evH[1], 0);
    projR_kernel<<<dim3(256, 4, 2), 256, 0, s2>>>(Wo, out, 1);

    // Spine level 0.
    projC_kernel<<<dim3(256, 4, 1), 256>>>(Wh, 1, 0);        // urgent C1 for 0
    cudaStreamWaitEvent(0, s_evGS[0], 0);
    seq_kernel<0><<<128, 128>>>(Wh);
    cudaEventRecord(s_evH[0], 0);
    cudaStreamWaitEvent(s2, s_evH[0], 0);
    projR_kernel<<<dim3(512, 4, 2), 256, 0, s2>>>(Wo, out, 0);  // writes Y
    cudaEventRecord(s_evR0, s2);

    finalH_kernel<<<dim3(8, 4), 256>>>(out);
    cudaStreamWaitEvent(0, s_evR0, 0);
}